// round 8
// baseline (speedup 1.0000x reference)
#include <cuda_runtime.h>
#include <cuda.h>
#include <cuda_fp16.h>
#include <cstdint>

// Vanilla tanh RNN: h_t = tanh(x_t W_ih^T + b_ih + h_{t-1} W_hh^T + b_hh)
// B=4096, T=256, I=H=64. Output: [hT (B*H) | all h_t (B*T*H)] fp32.
//
// WARP-SPECIALIZED version. Per block (16 batch rows, 64 threads):
//   warp 0 (consumer): register-resident recurrence. Per step: 32 MMA
//     (h-GEMM, acc preloaded from xW smem via LDS.128), tanh.approx.f32,
//     STS to swizzled out tile (TMA-stored every 4 steps), C-frag->A-frag
//     repack. No bias, no x work.
//   warp 1 (producer): TMA-loads x (2-step subtiles, double buffered),
//     computes xW_t = bias + x_t @ W_ih^T one 8-step chunk ahead into
//     double-buffered smem laid out EXACTLY as the consumer's acc fragments.
// Sync: 4 parity named barriers, once per 8-step chunk.

constexpr int Bsz = 4096, T = 256, H = 64;
constexpr int RPB = 16;               // batch rows per block
constexpr int GRID = Bsz / RPB;       // 256
constexpr int CH = 8, NCH = T / CH;   // xw chunking
constexpr int SM_XW = 0;              // [2 buf][8 step][32 lane][128B] = 64KB
constexpr int SM_X  = 65536;          // [2 buf][2 half][2 step][16*128B] = 16KB
constexpr int SM_O  = 81920;          // [2 half][4 step][16*128B] = 16KB
constexpr int SM_MB = 98304;          // 2 mbarriers
constexpr int SMEM_TOTAL = 98320;

__device__ __forceinline__ uint32_t packh2(float a, float b) {
    __half2 h = __floats2half2_rn(a, b);
    return *reinterpret_cast<uint32_t*>(&h);
}

__device__ __forceinline__ void mma16(float4& c, const uint32_t* a, const uint32_t* b) {
    asm volatile(
        "mma.sync.aligned.m16n8k16.row.col.f32.f16.f16.f32 "
        "{%0,%1,%2,%3}, {%4,%5,%6,%7}, {%8,%9}, {%0,%1,%2,%3};"
        : "+f"(c.x), "+f"(c.y), "+f"(c.z), "+f"(c.w)
        : "r"(a[0]), "r"(a[1]), "r"(a[2]), "r"(a[3]), "r"(b[0]), "r"(b[1]));
}

__device__ __forceinline__ float tanh_mufu(float z) {
    float r;
    asm("tanh.approx.f32 %0, %1;" : "=f"(r) : "f"(z));
    return r;
}

__device__ __forceinline__ void tma_load3d(uint32_t sdst, const CUtensorMap* m,
                                           int cx, int cy, int cz, uint32_t mbar) {
    asm volatile(
        "cp.async.bulk.tensor.3d.shared::cta.global.tile.mbarrier::complete_tx::bytes "
        "[%0], [%1, {%2, %3, %4}], [%5];"
        :: "r"(sdst), "l"(m), "r"(cx), "r"(cy), "r"(cz), "r"(mbar) : "memory");
}

__device__ __forceinline__ void tma_store3d(const CUtensorMap* m,
                                            int cx, int cy, int cz, uint32_t ssrc) {
    asm volatile(
        "cp.async.bulk.tensor.3d.global.shared::cta.tile.bulk_group "
        "[%0, {%1, %2, %3}], [%4];"
        :: "l"(m), "r"(cx), "r"(cy), "r"(cz), "r"(ssrc) : "memory");
}

__device__ __forceinline__ void mbar_wait(uint32_t mbar, int parity) {
    asm volatile(
        "{\n\t.reg .pred P;\n\t"
        "W%=:\n\t"
        "mbarrier.try_wait.parity.acquire.cta.shared::cta.b64 P, [%0], %1, 0x989680;\n\t"
        "@!P bra W%=;\n\t}"
        :: "r"(mbar), "r"(parity) : "memory");
}

#define BARSYNC(id) asm volatile("bar.sync %0, 64;"   :: "r"(id) : "memory")
#define BARARR(id)  asm volatile("bar.arrive %0, 64;" :: "r"(id) : "memory")
// ids: 1,2 = READY even/odd chunk; 3,4 = FREE even/odd chunk

__global__ void __launch_bounds__(64, 1)
rnn_fused(const __grid_constant__ CUtensorMap xmap,
          const __grid_constant__ CUtensorMap omap,
          const float* __restrict__ h0,
          const float* __restrict__ Wih, const float* __restrict__ Whh,
          const float* __restrict__ bih, const float* __restrict__ bhh,
          float* __restrict__ dout)
{
    extern __shared__ __align__(1024) char smem[];
    const uint32_t sb = (uint32_t)__cvta_generic_to_shared(smem);
    const uint32_t mb0 = sb + SM_MB, mb1 = sb + SM_MB + 8;

    const int tid  = threadIdx.x;
    const int lane = tid & 31;
    const int warp = tid >> 5;
    const int gid  = lane >> 2;   // 0..7
    const int tig  = lane & 3;    // 0..3
    const int b0   = blockIdx.x * RPB;
    const uint32_t key = (uint32_t)gid << 4;  // SW128 xor for rows gid, gid+8

    if (warp == 1) {
        // ======================= PRODUCER =======================
        if (lane == 0) {
            asm volatile("mbarrier.init.shared.b64 [%0], 1;" :: "r"(mb0));
            asm volatile("mbarrier.init.shared.b64 [%0], 1;" :: "r"(mb1));
            asm volatile("fence.proxy.async.shared::cta;" ::: "memory");
            // subs 0 (steps 0-1) -> stage 0, sub 1 (steps 2-3) -> stage 1
            asm volatile("mbarrier.arrive.expect_tx.shared.b64 _, [%0], %1;"
                         :: "r"(mb0), "r"(8192));
            tma_load3d(sb + SM_X + 0,    &xmap, 0,  b0, 0, mb0);
            tma_load3d(sb + SM_X + 4096, &xmap, 32, b0, 0, mb0);
            asm volatile("mbarrier.arrive.expect_tx.shared.b64 _, [%0], %1;"
                         :: "r"(mb1), "r"(8192));
            tma_load3d(sb + SM_X + 8192,  &xmap, 0,  b0, 2, mb1);
            tma_load3d(sb + SM_X + 12288, &xmap, 32, b0, 2, mb1);
        }
        __syncwarp();

        // W_ih B-fragments + bias
        uint32_t wih[8][4][2];
        float bias[8][2];
        #pragma unroll
        for (int nt = 0; nt < 8; ++nt) {
            const int n = nt * 8 + gid;
            #pragma unroll
            for (int kt = 0; kt < 4; ++kt) {
                const int k = kt * 16 + 2 * tig;
                wih[nt][kt][0] = packh2(Wih[n * H + k],     Wih[n * H + k + 1]);
                wih[nt][kt][1] = packh2(Wih[n * H + k + 8], Wih[n * H + k + 9]);
            }
            const int col = nt * 8 + 2 * tig;
            bias[nt][0] = bih[col]     + bhh[col];
            bias[nt][1] = bih[col + 1] + bhh[col + 1];
        }

        int ph0 = 0, ph1 = 0;
        for (int c = 0; c < NCH; ++c) {
            const int b = c & 1;
            if (c >= 2) BARSYNC(3 + b);          // consumer freed xw[b]
            #pragma unroll
            for (int tt = 0; tt < CH; ++tt) {
                const int sbuf = (tt >> 1) & 1;  // x stage parity (s = c*4+tt/2)
                if ((tt & 1) == 0) {
                    if (sbuf == 0) { mbar_wait(mb0, ph0); ph0 ^= 1; }
                    else           { mbar_wait(mb1, ph1); ph1 ^= 1; }
                }
                // pack x A-fragments from swizzled stage
                uint32_t xA[4][4];
                const char* tb = smem + SM_X + sbuf * 8192;
                #pragma unroll
                for (int kt = 0; kt < 4; ++kt) {
                    const int half = kt >> 1;
                    const uint32_t c4 = (uint32_t)(((kt & 1) * 16 + 2 * tig) * 4);
                    const char* base = tb + half * 4096 + (tt & 1) * 2048;
                    const uint32_t o0 = (uint32_t)(gid * 128) + c4;
                    float2 a0 = *(const float2*)(base + ((o0)        ^ key));
                    float2 a1 = *(const float2*)(base + ((o0 + 1024) ^ key));
                    float2 a2 = *(const float2*)(base + ((o0 + 32)   ^ key));
                    float2 a3 = *(const float2*)(base + ((o0 + 1056) ^ key));
                    xA[kt][0] = packh2(a0.x, a0.y);
                    xA[kt][1] = packh2(a1.x, a1.y);
                    xA[kt][2] = packh2(a2.x, a2.y);
                    xA[kt][3] = packh2(a3.x, a3.y);
                }
                // xw = bias + x @ W_ih^T
                float4 pacc[8];
                #pragma unroll
                for (int nt = 0; nt < 8; ++nt) {
                    pacc[nt].x = bias[nt][0]; pacc[nt].y = bias[nt][1];
                    pacc[nt].z = bias[nt][0]; pacc[nt].w = bias[nt][1];
                }
                #pragma unroll
                for (int nt = 0; nt < 8; ++nt)
                    #pragma unroll
                    for (int kt = 0; kt < 4; ++kt)
                        mma16(pacc[nt], xA[kt], wih[nt][kt]);
                // store in consumer acc-fragment layout
                float4* xwp = (float4*)(smem + SM_XW +
                                        (size_t)((b * CH + tt) * 32 + lane) * 128);
                #pragma unroll
                for (int nt = 0; nt < 8; ++nt) xwp[nt] = pacc[nt];

                // refill consumed stage with sub s+2
                if ((tt & 1) == 1 && lane == 0) {
                    const int s = c * 4 + (tt >> 1);
                    if (s + 2 < T / 2) {
                        const uint32_t mb = sbuf ? mb1 : mb0;
                        asm volatile("mbarrier.arrive.expect_tx.shared.b64 _, [%0], %1;"
                                     :: "r"(mb), "r"(8192));
                        tma_load3d(sb + SM_X + sbuf * 8192,        &xmap, 0,  b0, (s + 2) * 2, mb);
                        tma_load3d(sb + SM_X + sbuf * 8192 + 4096, &xmap, 32, b0, (s + 2) * 2, mb);
                    }
                }
            }
            BARARR(1 + b);                        // xw[b] ready
        }
    } else {
        // ======================= CONSUMER =======================
        uint32_t whh[8][4][2];
        #pragma unroll
        for (int nt = 0; nt < 8; ++nt) {
            const int n = nt * 8 + gid;
            #pragma unroll
            for (int kt = 0; kt < 4; ++kt) {
                const int k = kt * 16 + 2 * tig;
                whh[nt][kt][0] = packh2(Whh[n * H + k],     Whh[n * H + k + 1]);
                whh[nt][kt][1] = packh2(Whh[n * H + k + 8], Whh[n * H + k + 9]);
            }
        }
        const int row0 = b0 + gid;
        uint32_t hA[4][4];
        #pragma unroll
        for (int kt = 0; kt < 4; ++kt) {
            const int k = kt * 16 + 2 * tig;
            float2 v0 = *(const float2*)(h0 + (size_t)row0 * H + k);
            float2 v1 = *(const float2*)(h0 + (size_t)(row0 + 8) * H + k);
            float2 v2 = *(const float2*)(h0 + (size_t)row0 * H + k + 8);
            float2 v3 = *(const float2*)(h0 + (size_t)(row0 + 8) * H + k + 8);
            hA[kt][0] = packh2(v0.x, v0.y);
            hA[kt][1] = packh2(v1.x, v1.y);
            hA[kt][2] = packh2(v2.x, v2.y);
            hA[kt][3] = packh2(v3.x, v3.y);
        }

        for (int c = 0; c < NCH; ++c) {
            const int b = c & 1;
            BARSYNC(1 + b);                       // xw[b] ready
            float4 acc[2][8];
            {
                const float4* xp = (const float4*)(smem + SM_XW +
                                   (size_t)((b * CH) * 32 + lane) * 128);
                #pragma unroll
                for (int nt = 0; nt < 8; ++nt) acc[0][nt] = xp[nt];
            }
            #pragma unroll
            for (int tt = 0; tt < CH; ++tt) {
                const int bk = tt & 1;
                const int t  = c * CH + tt;
                // h-GEMM: acc += h_{t-1} @ W_hh^T
                #pragma unroll
                for (int nt = 0; nt < 8; ++nt)
                    #pragma unroll
                    for (int kt = 0; kt < 4; ++kt)
                        mma16(acc[bk][nt], hA[kt], whh[nt][kt]);
                // prefetch next step's xw init (off-chain)
                if (tt < CH - 1) {
                    const float4* xp = (const float4*)(smem + SM_XW +
                                       (size_t)((b * CH + tt + 1) * 32 + lane) * 128);
                    #pragma unroll
                    for (int nt = 0; nt < 8; ++nt) acc[bk ^ 1][nt] = xp[nt];
                }
                const int tl = t & 3;
                if (tl == 0) {   // out tile reusable once prior TMA store read it
                    if (lane == 0)
                        asm volatile("cp.async.bulk.wait_group.read 0;" ::: "memory");
                    __syncwarp();
                }
                // tanh -> out STS (swizzled) -> hA repack
                #pragma unroll
                for (int nt = 0; nt < 8; ++nt) {
                    const float v0 = tanh_mufu(acc[bk][nt].x);
                    const float v1 = tanh_mufu(acc[bk][nt].y);
                    const float v2 = tanh_mufu(acc[bk][nt].z);
                    const float v3 = tanh_mufu(acc[bk][nt].w);
                    char* ob = smem + SM_O + (nt >> 2) * 8192 + tl * 2048;
                    const uint32_t o0 = (uint32_t)(gid * 128 + ((nt & 3) * 8 + 2 * tig) * 4);
                    *(float2*)(ob + ((o0)        ^ key)) = make_float2(v0, v1);
                    *(float2*)(ob + ((o0 + 1024) ^ key)) = make_float2(v2, v3);
                    hA[nt >> 1][(nt & 1) * 2 + 0] = packh2(v0, v1);
                    hA[nt >> 1][(nt & 1) * 2 + 1] = packh2(v2, v3);
                    if (t == T - 1) {   // final hidden state
                        const int col = nt * 8 + 2 * tig;
                        *(float2*)(dout + (size_t)row0 * H + col) = make_float2(v0, v1);
                        *(float2*)(dout + (size_t)(row0 + 8) * H + col) = make_float2(v2, v3);
                    }
                }
                if (tl == 3) {
                    __syncwarp();
                    if (lane == 0) {
                        asm volatile("fence.proxy.async.shared::cta;" ::: "memory");
                        tma_store3d(&omap, 0,  b0, t - 3, sb + SM_O);
                        tma_store3d(&omap, 32, b0, t - 3, sb + SM_O + 8192);
                        asm volatile("cp.async.bulk.commit_group;" ::: "memory");
                    }
                    __syncwarp();
                }
            }
            BARARR(3 + b);                        // xw[b] free
        }
        if (lane == 0)
            asm volatile("cp.async.bulk.wait_group 0;" ::: "memory");
    }
}

typedef CUresult (*tmap_encode_fn)(
    CUtensorMap*, CUtensorMapDataType, cuuint32_t, void*,
    const cuuint64_t*, const cuuint64_t*, const cuuint32_t*, const cuuint32_t*,
    CUtensorMapInterleave, CUtensorMapSwizzle, CUtensorMapL2promotion,
    CUtensorMapFloatOOBfill);

extern "C" void kernel_launch(void* const* d_in, const int* in_sizes, int n_in,
                              void* d_out, int out_size) {
    const float* x   = (const float*)d_in[0];
    const float* h0  = (const float*)d_in[1];
    const float* Wih = (const float*)d_in[2];
    const float* Whh = (const float*)d_in[3];
    const float* bih = (const float*)d_in[4];
    const float* bhh = (const float*)d_in[5];
    float* dout = (float*)d_out;
    (void)in_sizes; (void)n_in; (void)out_size;

    void* fn = nullptr;
    cudaDriverEntryPointQueryResult qr;
    cudaGetDriverEntryPointByVersion("cuTensorMapEncodeTiled", &fn, 12000,
                                     cudaEnableDefault, &qr);
    tmap_encode_fn enc = (tmap_encode_fn)fn;

    // x and out are [B, T, 64] fp32; dims (h, b, t).
    cuuint64_t gdim[3] = {64, (cuuint64_t)Bsz, (cuuint64_t)T};
    cuuint64_t gstr[2] = {(cuuint64_t)T * H * sizeof(float),
                          (cuuint64_t)H * sizeof(float)};
    cuuint32_t xbox[3] = {32, RPB, 2};
    cuuint32_t obox[3] = {32, RPB, 4};
    cuuint32_t estr[3] = {1, 1, 1};

    CUtensorMap xmap, omap;
    enc(&xmap, CU_TENSOR_MAP_DATA_TYPE_FLOAT32, 3, (void*)x,
        gdim, gstr, xbox, estr, CU_TENSOR_MAP_INTERLEAVE_NONE,
        CU_TENSOR_MAP_SWIZZLE_128B, CU_TENSOR_MAP_L2_PROMOTION_L2_128B,
        CU_TENSOR_MAP_FLOAT_OOB_FILL_NONE);
    enc(&omap, CU_TENSOR_MAP_DATA_TYPE_FLOAT32, 3, (void*)(dout + (size_t)Bsz * H),
        gdim, gstr, obox, estr, CU_TENSOR_MAP_INTERLEAVE_NONE,
        CU_TENSOR_MAP_SWIZZLE_128B, CU_TENSOR_MAP_L2_PROMOTION_L2_128B,
        CU_TENSOR_MAP_FLOAT_OOB_FILL_NONE);

    cudaFuncSetAttribute(rnn_fused, cudaFuncAttributeMaxDynamicSharedMemorySize,
                         SMEM_TOTAL);
    rnn_fused<<<GRID, 64, SMEM_TOTAL>>>(xmap, omap, h0, Wih, Whh, bih, bhh, dout);
}

// round 9
// speedup vs baseline: 1.4200x; 1.4200x over previous
#include <cuda_runtime.h>
#include <cuda.h>
#include <cuda_fp16.h>
#include <cstdint>

// Vanilla tanh RNN: h_t = tanh(x_t W_ih^T + b_ih + h_{t-1} W_hh^T + b_hh)
// B=4096, T=256, I=H=64. Output: [hT (B*H) | all h_t (B*T*H)] fp32.
//
// R6 skeleton (best: 153us): register-resident recurrence per warp (C-frag of
// h_t == A-frag of next h-GEMM), TMA bulk I/O in 8-step chunks, 256 blocks x
// 32 threads. THIS ROUND: activation via tanh.approx.f16x2 — acc pairs are
// packed to half2 first, one MUFU op covers 2 values, and the packed result
// IS the hA fragment (repack eliminated). fp32 out values recovered by
// off-chain cvt.f32.f16.

constexpr int Bsz = 4096, T = 256, H = 64;
constexpr int RPB = 16;              // batch rows per block
constexpr int GRID = Bsz / RPB;      // 256
constexpr int CH  = 8;               // timesteps per chunk
constexpr int NCH = T / CH;          // 32
constexpr int XB  = 16384;           // bytes per half tile (128 rows x 128B)
constexpr int SM_X = 0;              // x tiles: [2 buf][2 half] = 64KB
constexpr int SM_O = 65536;          // out tile: [2 half] = 32KB
constexpr int SM_MB = 98304;         // mbarriers
constexpr int SMEM_TOTAL = 98432;

__device__ __forceinline__ uint32_t packh2(float a, float b) {
    __half2 h = __floats2half2_rn(a, b);
    return *reinterpret_cast<uint32_t*>(&h);
}

__device__ __forceinline__ uint32_t tanh_h2(uint32_t p) {
    uint32_t r;
    asm("tanh.approx.f16x2 %0, %1;" : "=r"(r) : "r"(p));
    return r;
}

__device__ __forceinline__ void mma16(float* c, const uint32_t* a, const uint32_t* b) {
    asm volatile(
        "mma.sync.aligned.m16n8k16.row.col.f32.f16.f16.f32 "
        "{%0,%1,%2,%3}, {%4,%5,%6,%7}, {%8,%9}, {%0,%1,%2,%3};"
        : "+f"(c[0]), "+f"(c[1]), "+f"(c[2]), "+f"(c[3])
        : "r"(a[0]), "r"(a[1]), "r"(a[2]), "r"(a[3]), "r"(b[0]), "r"(b[1]));
}

__device__ __forceinline__ void tma_load3d(uint32_t sdst, const CUtensorMap* m,
                                           int cx, int cy, int cz, uint32_t mbar) {
    asm volatile(
        "cp.async.bulk.tensor.3d.shared::cta.global.tile.mbarrier::complete_tx::bytes "
        "[%0], [%1, {%2, %3, %4}], [%5];"
        :: "r"(sdst), "l"(m), "r"(cx), "r"(cy), "r"(cz), "r"(mbar) : "memory");
}

__device__ __forceinline__ void tma_store3d(const CUtensorMap* m,
                                            int cx, int cy, int cz, uint32_t ssrc) {
    asm volatile(
        "cp.async.bulk.tensor.3d.global.shared::cta.tile.bulk_group "
        "[%0, {%1, %2, %3}], [%4];"
        :: "l"(m), "r"(cx), "r"(cy), "r"(cz), "r"(ssrc) : "memory");
}

__device__ __forceinline__ void mbar_wait(uint32_t mbar, int parity) {
    asm volatile(
        "{\n\t.reg .pred P;\n\t"
        "W%=:\n\t"
        "mbarrier.try_wait.parity.acquire.cta.shared::cta.b64 P, [%0], %1, 0x989680;\n\t"
        "@!P bra W%=;\n\t}"
        :: "r"(mbar), "r"(parity) : "memory");
}

__global__ void __launch_bounds__(32, 1)
rnn_fused(const __grid_constant__ CUtensorMap xmap,
          const __grid_constant__ CUtensorMap omap,
          const float* __restrict__ h0,
          const float* __restrict__ Wih, const float* __restrict__ Whh,
          const float* __restrict__ bih, const float* __restrict__ bhh,
          float* __restrict__ dout)
{
    extern __shared__ __align__(1024) char smem[];
    const uint32_t sb  = (uint32_t)__cvta_generic_to_shared(smem);
    const uint32_t mb0 = sb + SM_MB, mb1 = sb + SM_MB + 8;

    const int lane = threadIdx.x;
    const int gid  = lane >> 2;   // 0..7
    const int tig  = lane & 3;    // 0..3
    const int b0   = blockIdx.x * RPB;
    const int row0 = b0 + gid;
    const uint32_t key = (uint32_t)gid << 4;   // SW128 xor for rows gid, gid+8

    // ---- kick off TMA: mbar init + chunks 0,1 (before weight LDGs) ----
    if (lane == 0) {
        asm volatile("mbarrier.init.shared.b64 [%0], 1;" :: "r"(mb0));
        asm volatile("mbarrier.init.shared.b64 [%0], 1;" :: "r"(mb1));
        asm volatile("fence.proxy.async.shared::cta;" ::: "memory");
        asm volatile("mbarrier.arrive.expect_tx.shared.b64 _, [%0], %1;"
                     :: "r"(mb0), "r"(2 * XB));
        tma_load3d(sb + SM_X + 0,      &xmap, 0,  b0, 0, mb0);
        tma_load3d(sb + SM_X + XB,     &xmap, 32, b0, 0, mb0);
        asm volatile("mbarrier.arrive.expect_tx.shared.b64 _, [%0], %1;"
                     :: "r"(mb1), "r"(2 * XB));
        tma_load3d(sb + SM_X + 32768,      &xmap, 0,  b0, CH, mb1);
        tma_load3d(sb + SM_X + 32768 + XB, &xmap, 32, b0, CH, mb1);
    }

    // ---- weight B-fragments (fp16, register resident): [nt][kt][2] ----
    uint32_t wih[8][4][2], whh[8][4][2];
    #pragma unroll
    for (int nt = 0; nt < 8; ++nt) {
        const int n = nt * 8 + gid;
        #pragma unroll
        for (int kt = 0; kt < 4; ++kt) {
            const int k = kt * 16 + 2 * tig;
            wih[nt][kt][0] = packh2(Wih[n * H + k],     Wih[n * H + k + 1]);
            wih[nt][kt][1] = packh2(Wih[n * H + k + 8], Wih[n * H + k + 9]);
            whh[nt][kt][0] = packh2(Whh[n * H + k],     Whh[n * H + k + 1]);
            whh[nt][kt][1] = packh2(Whh[n * H + k + 8], Whh[n * H + k + 9]);
        }
    }
    float bias[8][2];
    #pragma unroll
    for (int nt = 0; nt < 8; ++nt) {
        const int col = nt * 8 + 2 * tig;
        bias[nt][0] = bih[col]     + bhh[col];
        bias[nt][1] = bih[col + 1] + bhh[col + 1];
    }

    // ---- hA = A-fragments of h (init h0) ----
    uint32_t hA[4][4];
    #pragma unroll
    for (int kt = 0; kt < 4; ++kt) {
        const int k = kt * 16 + 2 * tig;
        float2 v0 = *(const float2*)(h0 + (size_t)row0 * H + k);
        float2 v1 = *(const float2*)(h0 + (size_t)(row0 + 8) * H + k);
        float2 v2 = *(const float2*)(h0 + (size_t)row0 * H + k + 8);
        float2 v3 = *(const float2*)(h0 + (size_t)(row0 + 8) * H + k + 8);
        hA[kt][0] = packh2(v0.x, v0.y);
        hA[kt][1] = packh2(v1.x, v1.y);
        hA[kt][2] = packh2(v2.x, v2.y);
        hA[kt][3] = packh2(v3.x, v3.y);
    }

    // xA pack from swizzled x tile: buf in {0,1}, tt in [0,8)
    uint32_t xA[4][4];
    auto pack_xA = [&](int buf, int tt) {
        const char* tb = smem + SM_X + buf * 32768;
        #pragma unroll
        for (int kt = 0; kt < 4; ++kt) {
            const int half = kt >> 1;
            const uint32_t c4 = (uint32_t)(((kt & 1) * 16 + 2 * tig) * 4);
            const char* base = tb + half * XB + tt * 2048;
            const uint32_t o0 = (uint32_t)(gid * 128) + c4;
            float2 a0 = *(const float2*)(base + ((o0)          ^ key));
            float2 a1 = *(const float2*)(base + ((o0 + 1024)   ^ key));
            float2 a2 = *(const float2*)(base + ((o0 + 32)     ^ key));
            float2 a3 = *(const float2*)(base + ((o0 + 1056)   ^ key));
            xA[kt][0] = packh2(a0.x, a0.y);
            xA[kt][1] = packh2(a1.x, a1.y);
            xA[kt][2] = packh2(a2.x, a2.y);
            xA[kt][3] = packh2(a3.x, a3.y);
        }
    };

    // ---- prologue: wait x chunk0, acc = bias + x(0) @ W_ih^T ----
    mbar_wait(mb0, 0);
    int ph0 = 1, ph1 = 0;
    pack_xA(0, 0);
    float acc[8][4];
    #pragma unroll
    for (int nt = 0; nt < 8; ++nt) {
        acc[nt][0] = bias[nt][0]; acc[nt][1] = bias[nt][1];
        acc[nt][2] = bias[nt][0]; acc[nt][3] = bias[nt][1];
        #pragma unroll
        for (int kt = 0; kt < 4; ++kt)
            mma16(acc[nt], xA[kt], wih[nt][kt]);
    }

    for (int c = 0; c < NCH; ++c) {
        const int cur = c & 1;

        #pragma unroll
        for (int tt = 0; tt < CH; ++tt) {
            const int t = c * CH + tt;

            // ---- h-GEMM: acc += h_{t-1} @ W_hh^T ----
            #pragma unroll
            for (int nt = 0; nt < 8; ++nt)
                #pragma unroll
                for (int kt = 0; kt < 4; ++kt)
                    mma16(acc[nt], hA[kt], whh[nt][kt]);

            // ---- pack -> tanh.f16x2 (result IS hA) -> out cvt/STS ----
            #pragma unroll
            for (int nt = 0; nt < 8; ++nt) {
                const uint32_t t0 = tanh_h2(packh2(acc[nt][0], acc[nt][1]));
                const uint32_t t1 = tanh_h2(packh2(acc[nt][2], acc[nt][3]));
                hA[nt >> 1][(nt & 1) * 2 + 0] = t0;
                hA[nt >> 1][(nt & 1) * 2 + 1] = t1;
                // off-chain: fp32 out values
                const float2 f0 = __half22float2(*(const __half2*)&t0);
                const float2 f1 = __half22float2(*(const __half2*)&t1);
                char* ob = smem + SM_O + (nt >> 2) * XB + tt * 2048;
                const uint32_t o0 = (uint32_t)(gid * 128 + ((nt & 3) * 8 + 2 * tig) * 4);
                *(float2*)(ob + ((o0)        ^ key)) = f0;
                *(float2*)(ob + ((o0 + 1024) ^ key)) = f1;
                if (t == T - 1) {   // final hidden state, direct STG
                    const int col = nt * 8 + 2 * tig;
                    *(float2*)(dout + (size_t)row0 * H + col) = f0;
                    *(float2*)(dout + (size_t)(row0 + 8) * H + col) = f1;
                }
                acc[nt][0] = bias[nt][0]; acc[nt][1] = bias[nt][1];
                acc[nt][2] = bias[nt][0]; acc[nt][3] = bias[nt][1];
            }

            // ---- x-GEMM for t+1 (off the recurrence chain) ----
            if (t < T - 1) {
                if (tt == CH - 1) {
                    if (cur == 0) { mbar_wait(mb1, ph1); ph1 ^= 1; }
                    else          { mbar_wait(mb0, ph0); ph0 ^= 1; }
                    pack_xA(cur ^ 1, 0);
                } else {
                    pack_xA(cur, tt + 1);
                }
                #pragma unroll
                for (int nt = 0; nt < 8; ++nt)
                    #pragma unroll
                    for (int kt = 0; kt < 4; ++kt)
                        mma16(acc[nt], xA[kt], wih[nt][kt]);
            }
        }

        // ---- chunk epilogue: TMA store out, refill consumed x buffer ----
        __syncwarp();
        if (lane == 0) {
            asm volatile("fence.proxy.async.shared::cta;" ::: "memory");
            tma_store3d(&omap, 0,  b0, c * CH, sb + SM_O);
            tma_store3d(&omap, 32, b0, c * CH, sb + SM_O + XB);
            asm volatile("cp.async.bulk.commit_group;" ::: "memory");
            if (c + 2 < NCH) {
                const uint32_t mb = cur ? mb1 : mb0;
                asm volatile("mbarrier.arrive.expect_tx.shared.b64 _, [%0], %1;"
                             :: "r"(mb), "r"(2 * XB));
                tma_load3d(sb + SM_X + cur * 32768,      &xmap, 0,  b0, (c + 2) * CH, mb);
                tma_load3d(sb + SM_X + cur * 32768 + XB, &xmap, 32, b0, (c + 2) * CH, mb);
            }
            // out tile reusable once the store has READ smem
            asm volatile("cp.async.bulk.wait_group.read 0;" ::: "memory");
        }
        __syncwarp();
    }

    if (lane == 0)
        asm volatile("cp.async.bulk.wait_group 0;" ::: "memory");
}

typedef CUresult (*tmap_encode_fn)(
    CUtensorMap*, CUtensorMapDataType, cuuint32_t, void*,
    const cuuint64_t*, const cuuint64_t*, const cuuint32_t*, const cuuint32_t*,
    CUtensorMapInterleave, CUtensorMapSwizzle, CUtensorMapL2promotion,
    CUtensorMapFloatOOBfill);

extern "C" void kernel_launch(void* const* d_in, const int* in_sizes, int n_in,
                              void* d_out, int out_size) {
    const float* x   = (const float*)d_in[0];
    const float* h0  = (const float*)d_in[1];
    const float* Wih = (const float*)d_in[2];
    const float* Whh = (const float*)d_in[3];
    const float* bih = (const float*)d_in[4];
    const float* bhh = (const float*)d_in[5];
    float* dout = (float*)d_out;
    (void)in_sizes; (void)n_in; (void)out_size;

    // Tensor-map encoder via runtime entry point (no -lcuda needed).
    void* fn = nullptr;
    cudaDriverEntryPointQueryResult qr;
    cudaGetDriverEntryPointByVersion("cuTensorMapEncodeTiled", &fn, 12000,
                                     cudaEnableDefault, &qr);
    tmap_encode_fn enc = (tmap_encode_fn)fn;

    // Both x and out are [B, T, 64] fp32 row-major.
    // dims: (h=64, b=4096, t=256); strides: b->64KB, t->256B; box (32, 16, 8).
    cuuint64_t gdim[3] = {64, (cuuint64_t)Bsz, (cuuint64_t)T};
    cuuint64_t gstr[2] = {(cuuint64_t)T * H * sizeof(float),
                          (cuuint64_t)H * sizeof(float)};
    cuuint32_t box[3]  = {32, RPB, CH};
    cuuint32_t estr[3] = {1, 1, 1};

    CUtensorMap xmap, omap;
    enc(&xmap, CU_TENSOR_MAP_DATA_TYPE_FLOAT32, 3, (void*)x,
        gdim, gstr, box, estr, CU_TENSOR_MAP_INTERLEAVE_NONE,
        CU_TENSOR_MAP_SWIZZLE_128B, CU_TENSOR_MAP_L2_PROMOTION_L2_128B,
        CU_TENSOR_MAP_FLOAT_OOB_FILL_NONE);
    enc(&omap, CU_TENSOR_MAP_DATA_TYPE_FLOAT32, 3, (void*)(dout + (size_t)Bsz * H),
        gdim, gstr, box, estr, CU_TENSOR_MAP_INTERLEAVE_NONE,
        CU_TENSOR_MAP_SWIZZLE_128B, CU_TENSOR_MAP_L2_PROMOTION_L2_128B,
        CU_TENSOR_MAP_FLOAT_OOB_FILL_NONE);

    cudaFuncSetAttribute(rnn_fused, cudaFuncAttributeMaxDynamicSharedMemorySize,
                         SMEM_TOTAL);
    rnn_fused<<<GRID, 32, SMEM_TOTAL>>>(xmap, omap, h0, Wih, Whh, bih, bhh, dout);
}

// round 11
// speedup vs baseline: 1.9437x; 1.3688x over previous
#include <cuda_runtime.h>
#include <cuda.h>
#include <cuda_fp16.h>
#include <cstdint>

// Vanilla tanh RNN: h_t = tanh(x_t W_ih^T + b_ih + h_{t-1} W_hh^T + b_hh)
// B=4096, T=256, I=H=64. Output: [hT (B*H) | all h_t (B*T*H)] fp32.
//
// 4-WAY N-SPLIT: 256 blocks x 128 threads. A block owns 16 batch rows; each
// of its 4 warps owns 16 of the 64 hidden cols -> 16 MMA/warp/step spread
// over 4 SMSPs. h_t round-trips a double-buffered padded fp16 smem tile
// (STS -> barrier -> ldmatrix.x4). x arrives via TMA (4-step fp32 chunks,
// double buffered) converted once to padded fp16 tiles; out staged in
// swizzled fp32 tiles (triple buffered), TMA-stored per chunk.
//
// R9 -> R10 fix: chunk c+2 TMA load was guarded by c>0, so chunk 2 was never
// loaded -> mbarrier deadlock at c=1. Load now issued at every chunk start.

constexpr int Bsz = 4096, T = 256, H = 64;
constexpr int RPB = 16, GRID = Bsz / RPB;     // 256 blocks
constexpr int CH = 4, NCH = T / CH;           // 64 chunks
// smem byte offsets
constexpr int SM_X32 = 0;        // [2][16384] fp32 x staging (TMA, SW128)
constexpr int SM_X16 = 32768;    // [2][4 step][16 rows * 144B] fp16 x tiles
constexpr int SM_H   = 51200;    // [2][16 * 144B] fp16 h tiles
constexpr int SM_O   = 56320;    // [3][16384] fp32 out staging (SW128)
constexpr int SM_MB  = 105472;   // 2 mbarriers
constexpr int SMEM_TOTAL = 105488;

__device__ __forceinline__ uint32_t packh2(float a, float b) {
    __half2 h = __floats2half2_rn(a, b);
    return *reinterpret_cast<uint32_t*>(&h);
}

__device__ __forceinline__ void mma16(float* c, const uint32_t* a, const uint32_t* b) {
    asm volatile(
        "mma.sync.aligned.m16n8k16.row.col.f32.f16.f16.f32 "
        "{%0,%1,%2,%3}, {%4,%5,%6,%7}, {%8,%9}, {%0,%1,%2,%3};"
        : "+f"(c[0]), "+f"(c[1]), "+f"(c[2]), "+f"(c[3])
        : "r"(a[0]), "r"(a[1]), "r"(a[2]), "r"(a[3]), "r"(b[0]), "r"(b[1]));
}

__device__ __forceinline__ void ldsm4(uint32_t* a, uint32_t addr) {
    asm volatile("ldmatrix.sync.aligned.m8n8.x4.shared.b16 {%0,%1,%2,%3}, [%4];"
                 : "=r"(a[0]), "=r"(a[1]), "=r"(a[2]), "=r"(a[3])
                 : "r"(addr));
}

__device__ __forceinline__ float tanh_mufu(float z) {
    float r;
    asm("tanh.approx.f32 %0, %1;" : "=f"(r) : "f"(z));
    return r;
}

__device__ __forceinline__ void tma_load3d(uint32_t sdst, const CUtensorMap* m,
                                           int cx, int cy, int cz, uint32_t mbar) {
    asm volatile(
        "cp.async.bulk.tensor.3d.shared::cta.global.tile.mbarrier::complete_tx::bytes "
        "[%0], [%1, {%2, %3, %4}], [%5];"
        :: "r"(sdst), "l"(m), "r"(cx), "r"(cy), "r"(cz), "r"(mbar) : "memory");
}

__device__ __forceinline__ void tma_store3d(const CUtensorMap* m,
                                            int cx, int cy, int cz, uint32_t ssrc) {
    asm volatile(
        "cp.async.bulk.tensor.3d.global.shared::cta.tile.bulk_group "
        "[%0, {%1, %2, %3}], [%4];"
        :: "l"(m), "r"(cx), "r"(cy), "r"(cz), "r"(ssrc) : "memory");
}

__device__ __forceinline__ void mbar_wait(uint32_t mbar, int parity) {
    asm volatile(
        "{\n\t.reg .pred P;\n\t"
        "W%=:\n\t"
        "mbarrier.try_wait.parity.acquire.cta.shared::cta.b64 P, [%0], %1, 0x989680;\n\t"
        "@!P bra W%=;\n\t}"
        :: "r"(mbar), "r"(parity) : "memory");
}

__global__ void __launch_bounds__(128, 2)
rnn_fused(const __grid_constant__ CUtensorMap xmap,
          const __grid_constant__ CUtensorMap omap,
          const float* __restrict__ h0,
          const float* __restrict__ Wih, const float* __restrict__ Whh,
          const float* __restrict__ bih, const float* __restrict__ bhh,
          float* __restrict__ dout)
{
    extern __shared__ __align__(1024) char smem[];
    const uint32_t sb = (uint32_t)__cvta_generic_to_shared(smem);
    const uint32_t mbA[2] = {sb + SM_MB, sb + SM_MB + 8};

    const int tid  = threadIdx.x;
    const int lane = tid & 31;
    const int q    = tid >> 5;          // warp = col group (16 cols)
    const int gid  = lane >> 2;
    const int tig  = lane & 3;
    const int b0   = blockIdx.x * RPB;
    const int row0 = b0 + gid;

    // ---- TMA prologue: mbars + chunks 0,1 ----
    if (tid == 0) {
        asm volatile("mbarrier.init.shared.b64 [%0], 1;" :: "r"(mbA[0]));
        asm volatile("mbarrier.init.shared.b64 [%0], 1;" :: "r"(mbA[1]));
        asm volatile("fence.proxy.async.shared::cta;" ::: "memory");
        asm volatile("mbarrier.arrive.expect_tx.shared.b64 _, [%0], %1;"
                     :: "r"(mbA[0]), "r"(16384));
        tma_load3d(sb + SM_X32,        &xmap, 0,  b0, 0, mbA[0]);
        tma_load3d(sb + SM_X32 + 8192, &xmap, 32, b0, 0, mbA[0]);
        asm volatile("mbarrier.arrive.expect_tx.shared.b64 _, [%0], %1;"
                     :: "r"(mbA[1]), "r"(16384));
        tma_load3d(sb + SM_X32 + 16384, &xmap, 0,  b0, CH, mbA[1]);
        tma_load3d(sb + SM_X32 + 24576, &xmap, 32, b0, CH, mbA[1]);
    }
    __syncthreads();   // mbar init visible to all before any wait

    // ---- weights for this warp's 16 cols ----
    uint32_t wih[2][4][2], whh[2][4][2];
    float bias[2][2];
    #pragma unroll
    for (int nt = 0; nt < 2; ++nt) {
        const int n = q * 16 + nt * 8 + gid;
        #pragma unroll
        for (int kt = 0; kt < 4; ++kt) {
            const int k = kt * 16 + 2 * tig;
            wih[nt][kt][0] = packh2(Wih[n * H + k],     Wih[n * H + k + 1]);
            wih[nt][kt][1] = packh2(Wih[n * H + k + 8], Wih[n * H + k + 9]);
            whh[nt][kt][0] = packh2(Whh[n * H + k],     Whh[n * H + k + 1]);
            whh[nt][kt][1] = packh2(Whh[n * H + k + 8], Whh[n * H + k + 9]);
        }
        const int col = q * 16 + nt * 8 + 2 * tig;
        bias[nt][0] = bih[col]     + bhh[col];
        bias[nt][1] = bih[col + 1] + bhh[col + 1];
    }

    // ---- h0 -> hbuf[0] (padded fp16 tile, 144B rows) ----
    {
        const int r = tid >> 3, g8 = tid & 7;
        const float* hp = h0 + (size_t)(b0 + r) * H + g8 * 8;
        float4 a = *(const float4*)hp, b2 = *(const float4*)(hp + 4);
        *(uint4*)(smem + SM_H + r * 144 + g8 * 16) =
            make_uint4(packh2(a.x, a.y), packh2(a.z, a.w),
                       packh2(b2.x, b2.y), packh2(b2.z, b2.w));
    }

    // ---- fp32->fp16 x conversion (thread covers row cr, 8 float cols) ----
    const int cr = tid >> 3, cg = tid & 7;
    const int chalf = cg >> 2;
    auto convert = [&](int buf, int step) {
        const char* src = smem + SM_X32 + buf * 16384 + chalf * 8192 + step * 2048;
        const uint32_t o = (uint32_t)(cr * 128 + (cg & 3) * 32);
        const uint32_t k = (uint32_t)((cr & 7) << 4);
        float4 a  = *(const float4*)(src + ((o)      ^ k));
        float4 b2 = *(const float4*)(src + ((o + 16) ^ k));
        *(uint4*)(smem + SM_X16 + buf * 9216 + step * 2304 + cr * 144 + cg * 16) =
            make_uint4(packh2(a.x, a.y), packh2(a.z, a.w),
                       packh2(b2.x, b2.y), packh2(b2.z, b2.w));
    };

    // ldmatrix lane offset within a 16x64h padded tile
    const int mat = lane >> 3, mr = lane & 7;
    const uint32_t aoff = (uint32_t)(((mat & 1) * 8 + mr) * 144 + (mat >> 1) * 16);
    const uint32_t x16b = sb + SM_X16;
    const uint32_t hbB  = sb + SM_H;

    // ---- prologue: wait chunk0, convert it, initial acc = bias + xW(0) ----
    mbar_wait(mbA[0], 0);
    #pragma unroll
    for (int s = 0; s < CH; ++s) convert(0, s);
    __syncthreads();

    float acc[2][4];
    #pragma unroll
    for (int nt = 0; nt < 2; ++nt) {
        acc[nt][0] = bias[nt][0]; acc[nt][1] = bias[nt][1];
        acc[nt][2] = bias[nt][0]; acc[nt][3] = bias[nt][1];
    }
    #pragma unroll
    for (int kt = 0; kt < 4; ++kt) {
        uint32_t a[4];
        ldsm4(a, x16b + aoff + kt * 32);
        mma16(acc[0], a, wih[0][kt]);
        mma16(acc[1], a, wih[1][kt]);
    }

    int ph[2] = {1, 0};   // next parities for mb0/mb1

    for (int t = 0; t < T; ++t) {
        const int tl = t & 3, c = t >> 2, cb = c & 1, nb = cb ^ 1, pb = t & 1;

        // ---- chunk-start TMA bookkeeping ----
        // FIX vs R9: the load of chunk c+2 must run for ALL c (incl. c=0);
        // x32[cb]'s chunk-c data was fully converted during chunk c-1.
        if (tl == 0 && tid == 0) {
            if (c > 0) {
                asm volatile("fence.proxy.async.shared::cta;" ::: "memory");
                const int pc = c - 1;
                const uint32_t osrc = sb + SM_O + (pc % 3) * 16384;
                tma_store3d(&omap, 0,  b0, pc * CH, osrc);
                tma_store3d(&omap, 32, b0, pc * CH, osrc + 8192);
                asm volatile("cp.async.bulk.commit_group;" ::: "memory");
            }
            if (c + 2 < NCH) {
                asm volatile("mbarrier.arrive.expect_tx.shared.b64 _, [%0], %1;"
                             :: "r"(mbA[cb]), "r"(16384));
                tma_load3d(sb + SM_X32 + cb * 16384,        &xmap, 0,  b0, (c + 2) * CH, mbA[cb]);
                tma_load3d(sb + SM_X32 + cb * 16384 + 8192, &xmap, 32, b0, (c + 2) * CH, mbA[cb]);
            }
            if (c > 0)
                asm volatile("cp.async.bulk.wait_group.read 1;" ::: "memory");
        }
        if (tl == 0 && c + 1 < NCH) { mbar_wait(mbA[nb], ph[nb]); ph[nb] ^= 1; }

        // ---- h-GEMM: acc += h_{t-1} @ W_hh^T (ldmatrix from hbuf[pb]) ----
        {
            const uint32_t hrd = hbB + pb * 2304 + aoff;
            #pragma unroll
            for (int kt = 0; kt < 4; ++kt) {
                uint32_t a[4];
                ldsm4(a, hrd + kt * 32);
                mma16(acc[0], a, whh[0][kt]);
                mma16(acc[1], a, whh[1][kt]);
            }
        }

        // ---- tanh -> publish h (STS) + out staging (STS, swizzled) ----
        {
            uint32_t* hw = (uint32_t*)(smem + SM_H + (pb ^ 1) * 2304);
            char* otile = smem + SM_O + (c % 3) * 16384 + tl * 2048;
            const uint32_t k2 = (uint32_t)(gid << 4);
            #pragma unroll
            for (int nt = 0; nt < 2; ++nt) {
                const float v0 = tanh_mufu(acc[nt][0]);
                const float v1 = tanh_mufu(acc[nt][1]);
                const float v2 = tanh_mufu(acc[nt][2]);
                const float v3 = tanh_mufu(acc[nt][3]);
                hw[gid * 36 + q * 8 + nt * 4 + tig]       = packh2(v0, v1);
                hw[(gid + 8) * 36 + q * 8 + nt * 4 + tig] = packh2(v2, v3);
                const int col = q * 16 + nt * 8 + 2 * tig;
                char* oh = otile + (col >> 5) * 8192;
                const uint32_t co = (uint32_t)((col & 31) * 4);
                *(float2*)(oh + ((gid * 128 + co) ^ k2))       = make_float2(v0, v1);
                *(float2*)(oh + (((gid + 8) * 128 + co) ^ k2)) = make_float2(v2, v3);
                if (t == T - 1) {
                    *(float2*)(dout + (size_t)row0 * H + col)       = make_float2(v0, v1);
                    *(float2*)(dout + (size_t)(row0 + 8) * H + col) = make_float2(v2, v3);
                }
                acc[nt][0] = bias[nt][0]; acc[nt][1] = bias[nt][1];
                acc[nt][2] = bias[nt][0]; acc[nt][3] = bias[nt][1];
            }
        }

        // ---- x-GEMM for t+1 (independent of the h chain) ----
        if (t + 1 < T) {
            const uint32_t xrd = x16b +
                ((tl < 3) ? (uint32_t)(cb * 9216 + (tl + 1) * 2304)
                          : (uint32_t)(nb * 9216)) + aoff;
            #pragma unroll
            for (int kt = 0; kt < 4; ++kt) {
                uint32_t a[4];
                ldsm4(a, xrd + kt * 32);
                mma16(acc[0], a, wih[0][kt]);
                mma16(acc[1], a, wih[1][kt]);
            }
        }

        // ---- convert step tl of next chunk (off-chain) ----
        if (c + 1 < NCH) convert(nb, tl);

        __syncthreads();
    }

    // ---- final chunk store ----
    if (tid == 0) {
        asm volatile("fence.proxy.async.shared::cta;" ::: "memory");
        const int pc = NCH - 1;
        const uint32_t osrc = sb + SM_O + (pc % 3) * 16384;
        tma_store3d(&omap, 0,  b0, pc * CH, osrc);
        tma_store3d(&omap, 32, b0, pc * CH, osrc + 8192);
        asm volatile("cp.async.bulk.commit_group;" ::: "memory");
        asm volatile("cp.async.bulk.wait_group 0;" ::: "memory");
    }
}

typedef CUresult (*tmap_encode_fn)(
    CUtensorMap*, CUtensorMapDataType, cuuint32_t, void*,
    const cuuint64_t*, const cuuint64_t*, const cuuint32_t*, const cuuint32_t*,
    CUtensorMapInterleave, CUtensorMapSwizzle, CUtensorMapL2promotion,
    CUtensorMapFloatOOBfill);

extern "C" void kernel_launch(void* const* d_in, const int* in_sizes, int n_in,
                              void* d_out, int out_size) {
    const float* x   = (const float*)d_in[0];
    const float* h0  = (const float*)d_in[1];
    const float* Wih = (const float*)d_in[2];
    const float* Whh = (const float*)d_in[3];
    const float* bih = (const float*)d_in[4];
    const float* bhh = (const float*)d_in[5];
    float* dout = (float*)d_out;
    (void)in_sizes; (void)n_in; (void)out_size;

    void* fn = nullptr;
    cudaDriverEntryPointQueryResult qr;
    cudaGetDriverEntryPointByVersion("cuTensorMapEncodeTiled", &fn, 12000,
                                     cudaEnableDefault, &qr);
    tmap_encode_fn enc = (tmap_encode_fn)fn;

    // x and out are [B, T, 64] fp32; dims (h, b, t); box (32, 16, 4), SW128.
    cuuint64_t gdim[3] = {64, (cuuint64_t)Bsz, (cuuint64_t)T};
    cuuint64_t gstr[2] = {(cuuint64_t)T * H * sizeof(float),
                          (cuuint64_t)H * sizeof(float)};
    cuuint32_t box[3]  = {32, RPB, CH};
    cuuint32_t estr[3] = {1, 1, 1};

    CUtensorMap xmap, omap;
    enc(&xmap, CU_TENSOR_MAP_DATA_TYPE_FLOAT32, 3, (void*)x,
        gdim, gstr, box, estr, CU_TENSOR_MAP_INTERLEAVE_NONE,
        CU_TENSOR_MAP_SWIZZLE_128B, CU_TENSOR_MAP_L2_PROMOTION_L2_128B,
        CU_TENSOR_MAP_FLOAT_OOB_FILL_NONE);
    enc(&omap, CU_TENSOR_MAP_DATA_TYPE_FLOAT32, 3, (void*)(dout + (size_t)Bsz * H),
        gdim, gstr, box, estr, CU_TENSOR_MAP_INTERLEAVE_NONE,
        CU_TENSOR_MAP_SWIZZLE_128B, CU_TENSOR_MAP_L2_PROMOTION_L2_128B,
        CU_TENSOR_MAP_FLOAT_OOB_FILL_NONE);

    cudaFuncSetAttribute(rnn_fused, cudaFuncAttributeMaxDynamicSharedMemorySize,
                         SMEM_TOTAL);
    rnn_fused<<<GRID, 128, SMEM_TOTAL>>>(xmap, omap, h0, Wih, Whh, bih, bhh, dout);
}